// round 12
// baseline (speedup 1.0000x reference)
#include <cuda_runtime.h>
#include <cuda_bf16.h>
#include <math.h>
#include <stdint.h>

// Problem constants (fixed shapes)
#define BB 4
#define SS 2048
#define DM 1024
#define NH 16
#define HD 64
#define MROWS (BB * SS)   // 8192
#define TT 64             // chunk length
#define NCH (SS / TT)     // 32 chunks
#define HG (BB * NH)      // 64 global heads
#define CP 68             // smem tile pitch (floats), 16B-aligned rows

// ---------------- scratch (static __device__, no allocation) ----------------
__device__ float g_q[MROWS * DM];
__device__ float g_k[MROWS * DM];
__device__ float g_v[MROWS * DM];
__device__ float g_attn[MROWS * DM];
__device__ float g_beta[MROWS * NH];
__device__ float g_invrms[MROWS];

// chunked-recurrence scratch
__device__ float g_CC[(size_t)HG * NCH * TT * TT];   // K K^T grams
__device__ float g_M0[(size_t)HG * NCH * HD * HD];   // chunk-entry state, TRANSPOSED: MT[d][h]
__device__ float g_dlt[(size_t)HG * NCH * TT * HD];  // per-chunk Delta rows

// bf16 hi/lo split planes
__device__ __nv_bfloat16 g_Whi[4 * DM * DM];
__device__ __nv_bfloat16 g_Wlo[4 * DM * DM];
__device__ __nv_bfloat16 g_xhi[MROWS * DM];
__device__ __nv_bfloat16 g_xlo[MROWS * DM];
__device__ __nv_bfloat16 g_ahi[MROWS * DM];
__device__ __nv_bfloat16 g_alo[MROWS * DM];

// ---------------- bf16 split helper -----------------------------------------
__device__ __forceinline__ void bsplit4(float4 v, uint32_t* hi, uint32_t* lo)
{
    __nv_bfloat162 h01 = __floats2bfloat162_rn(v.x, v.y);
    __nv_bfloat162 h23 = __floats2bfloat162_rn(v.z, v.w);
    float2 f01 = __bfloat1622float2(h01);
    float2 f23 = __bfloat1622float2(h23);
    __nv_bfloat162 l01 = __floats2bfloat162_rn(v.x - f01.x, v.y - f01.y);
    __nv_bfloat162 l23 = __floats2bfloat162_rn(v.z - f23.x, v.w - f23.y);
    hi[0] = *(uint32_t*)&h01; hi[1] = *(uint32_t*)&h23;
    lo[0] = *(uint32_t*)&l01; lo[1] = *(uint32_t*)&l23;
}

// ---------------- one-shot split kernels -------------------------------------
__global__ __launch_bounds__(256)
void split_w_kernel(const float* __restrict__ Wq, const float* __restrict__ Wk,
                    const float* __restrict__ Wv, const float* __restrict__ Wo)
{
    const float* W = (blockIdx.y == 0) ? Wq : (blockIdx.y == 1) ? Wk
                   : (blockIdx.y == 2) ? Wv : Wo;
    size_t i = (size_t)blockIdx.x * 256 + threadIdx.x;
    float4 v = ((const float4*)W)[i];
    uint32_t hi[2], lo[2];
    bsplit4(v, hi, lo);
    size_t base = (size_t)blockIdx.y * (DM * DM / 4);
    ((uint2*)g_Whi)[base + i] = make_uint2(hi[0], hi[1]);
    ((uint2*)g_Wlo)[base + i] = make_uint2(lo[0], lo[1]);
}

__global__ __launch_bounds__(256)
void split_x_kernel(const float* __restrict__ x)
{
    size_t i = (size_t)blockIdx.x * 256 + threadIdx.x;
    float4 v = ((const float4*)x)[i];
    uint32_t hi[2], lo[2];
    bsplit4(v, hi, lo);
    ((uint2*)g_xhi)[i] = make_uint2(hi[0], hi[1]);
    ((uint2*)g_xlo)[i] = make_uint2(lo[0], lo[1]);
}

// attn * invrms[row] * rmsw[col], then split (fused rmsnorm)
__global__ __launch_bounds__(256)
void split_attn_kernel(const float* __restrict__ rmsw)
{
    size_t i = (size_t)blockIdx.x * 256 + threadIdx.x;
    int row = (int)(i >> 8);
    int c4 = (int)(i & 255);
    float4 v = ((const float4*)g_attn)[i];
    float s = g_invrms[row];
    float4 w = ((const float4*)rmsw)[c4];
    v.x *= s * w.x; v.y *= s * w.y; v.z *= s * w.z; v.w *= s * w.w;
    uint32_t hi[2], lo[2];
    bsplit4(v, hi, lo);
    ((uint2*)g_ahi)[i] = make_uint2(hi[0], hi[1]);
    ((uint2*)g_alo)[i] = make_uint2(lo[0], lo[1]);
}

// ---------------- tensor-core GEMM: C = epi(A[M,K] @ B[N,K]^T) --------------
#define RBK 16
#define RBP 24

__device__ __forceinline__ void mma_bf16(float* c, const uint32_t* a,
                                         uint32_t b0, uint32_t b1)
{
    asm volatile(
        "mma.sync.aligned.m16n8k16.row.col.f32.bf16.bf16.f32 "
        "{%0,%1,%2,%3},{%4,%5,%6,%7},{%8,%9},{%0,%1,%2,%3};"
        : "+f"(c[0]), "+f"(c[1]), "+f"(c[2]), "+f"(c[3])
        : "r"(a[0]), "r"(a[1]), "r"(a[2]), "r"(a[3]), "r"(b0), "r"(b1));
}

__device__ __forceinline__
void mma_gemm_body(const __nv_bfloat16* __restrict__ Ahi,
                   const __nv_bfloat16* __restrict__ Alo,
                   const __nv_bfloat16* __restrict__ Bhi,
                   const __nv_bfloat16* __restrict__ Blo,
                   float* __restrict__ C, int epi_mode)
{
    const int K = DM, N = DM;
    __shared__ __align__(16) __nv_bfloat16 Ah[128][RBP];
    __shared__ __align__(16) __nv_bfloat16 Al[128][RBP];
    __shared__ __align__(16) __nv_bfloat16 Bh[128][RBP];
    __shared__ __align__(16) __nv_bfloat16 Bl[128][RBP];

    const int tid = threadIdx.x;
    const int lane = tid & 31;
    const int warp = tid >> 5;
    const int warp_m = warp & 3;
    const int warp_n = warp >> 2;
    const int g = lane >> 2;
    const int tg = lane & 3;

    const int bm0 = blockIdx.y * 128;
    const int bn0 = blockIdx.x * 128;

    const int srow = tid >> 1;
    const int shalf = (tid & 1) * 8;
    const size_t aoff = (size_t)(bm0 + srow) * K + shalf;
    const size_t boff = (size_t)(bn0 + srow) * K + shalf;

    float acc[2][8][4];
#pragma unroll
    for (int mt = 0; mt < 2; mt++)
#pragma unroll
        for (int nt = 0; nt < 8; nt++)
#pragma unroll
            for (int r = 0; r < 4; r++) acc[mt][nt][r] = 0.f;

    uint4 vah = *(const uint4*)(Ahi + aoff);
    uint4 val = *(const uint4*)(Alo + aoff);
    uint4 vbh = *(const uint4*)(Bhi + boff);
    uint4 vbl = *(const uint4*)(Blo + boff);

    for (int k0 = 0; k0 < K; k0 += RBK) {
        *(uint4*)&Ah[srow][shalf] = vah;
        *(uint4*)&Al[srow][shalf] = val;
        *(uint4*)&Bh[srow][shalf] = vbh;
        *(uint4*)&Bl[srow][shalf] = vbl;
        __syncthreads();

        if (k0 + RBK < K) {
            vah = *(const uint4*)(Ahi + aoff + k0 + RBK);
            val = *(const uint4*)(Alo + aoff + k0 + RBK);
            vbh = *(const uint4*)(Bhi + boff + k0 + RBK);
            vbl = *(const uint4*)(Blo + boff + k0 + RBK);
        }

        uint32_t ah[2][4], al[2][4];
#pragma unroll
        for (int mt = 0; mt < 2; mt++) {
            int mr = warp_m * 32 + mt * 16 + g;
            ah[mt][0] = *(const uint32_t*)&Ah[mr][2 * tg];
            ah[mt][1] = *(const uint32_t*)&Ah[mr + 8][2 * tg];
            ah[mt][2] = *(const uint32_t*)&Ah[mr][8 + 2 * tg];
            ah[mt][3] = *(const uint32_t*)&Ah[mr + 8][8 + 2 * tg];
            al[mt][0] = *(const uint32_t*)&Al[mr][2 * tg];
            al[mt][1] = *(const uint32_t*)&Al[mr + 8][2 * tg];
            al[mt][2] = *(const uint32_t*)&Al[mr][8 + 2 * tg];
            al[mt][3] = *(const uint32_t*)&Al[mr + 8][8 + 2 * tg];
        }
#pragma unroll
        for (int nt = 0; nt < 8; nt++) {
            int nr = warp_n * 64 + nt * 8 + g;
            uint32_t bh0 = *(const uint32_t*)&Bh[nr][2 * tg];
            uint32_t bh1 = *(const uint32_t*)&Bh[nr][8 + 2 * tg];
            uint32_t bl0 = *(const uint32_t*)&Bl[nr][2 * tg];
            uint32_t bl1 = *(const uint32_t*)&Bl[nr][8 + 2 * tg];
#pragma unroll
            for (int mt = 0; mt < 2; mt++) {
                mma_bf16(acc[mt][nt], ah[mt], bh0, bh1);
                mma_bf16(acc[mt][nt], ah[mt], bl0, bl1);
                mma_bf16(acc[mt][nt], al[mt], bh0, bh1);
            }
        }
        __syncthreads();
    }

    float v[2][8][4];
#pragma unroll
    for (int mt = 0; mt < 2; mt++)
#pragma unroll
        for (int nt = 0; nt < 8; nt++)
#pragma unroll
            for (int r = 0; r < 4; r++) {
                float x = acc[mt][nt][r];
                if (epi_mode >= 1) x = x / (1.f + expf(-x));
                v[mt][nt][r] = x;
            }

    if (epi_mode == 2) {
#pragma unroll
        for (int mt = 0; mt < 2; mt++) {
            float s0 = 0.f, s1 = 0.f;
#pragma unroll
            for (int nt = 0; nt < 8; nt++) {
                s0 = fmaf(v[mt][nt][0], v[mt][nt][0],
                     fmaf(v[mt][nt][1], v[mt][nt][1], s0));
                s1 = fmaf(v[mt][nt][2], v[mt][nt][2],
                     fmaf(v[mt][nt][3], v[mt][nt][3], s1));
            }
            s0 += __shfl_xor_sync(0xffffffffu, s0, 1);
            s0 += __shfl_xor_sync(0xffffffffu, s0, 2);
            s1 += __shfl_xor_sync(0xffffffffu, s1, 1);
            s1 += __shfl_xor_sync(0xffffffffu, s1, 2);
            float i0 = 1.f / (sqrtf(s0) + 1e-6f);
            float i1 = 1.f / (sqrtf(s1) + 1e-6f);
#pragma unroll
            for (int nt = 0; nt < 8; nt++) {
                v[mt][nt][0] *= i0; v[mt][nt][1] *= i0;
                v[mt][nt][2] *= i1; v[mt][nt][3] *= i1;
            }
        }
    }

#pragma unroll
    for (int mt = 0; mt < 2; mt++)
#pragma unroll
        for (int nt = 0; nt < 8; nt++) {
            int row0 = bm0 + warp_m * 32 + mt * 16 + g;
            int cb = bn0 + warp_n * 64 + nt * 8 + 2 * tg;
            *(float2*)(C + (size_t)row0 * N + cb)       = make_float2(v[mt][nt][0], v[mt][nt][1]);
            *(float2*)(C + (size_t)(row0 + 8) * N + cb) = make_float2(v[mt][nt][2], v[mt][nt][3]);
        }
}

__global__ __launch_bounds__(256, 2)
void mma_qkv()
{
    const size_t wb = (size_t)blockIdx.z * DM * DM;
    if (blockIdx.z == 0)      mma_gemm_body(g_xhi, g_xlo, g_Whi + wb, g_Wlo + wb, g_q, 2);
    else if (blockIdx.z == 1) mma_gemm_body(g_xhi, g_xlo, g_Whi + wb, g_Wlo + wb, g_k, 2);
    else                      mma_gemm_body(g_xhi, g_xlo, g_Whi + wb, g_Wlo + wb, g_v, 1);
}

__global__ __launch_bounds__(256, 2)
void mma_o(float* __restrict__ outp)
{
    const size_t wb = (size_t)3 * DM * DM;
    mma_gemm_body(g_ahi, g_alo, g_Whi + wb, g_Wlo + wb, outp, 0);
}

// ---------------- beta: sigmoid(x @ Wbeta^T), (8192,16) ---------------------
__global__ __launch_bounds__(512)
void beta_kernel(const float* __restrict__ x, const float* __restrict__ Wb)
{
    __shared__ __align__(16) float sx[DM];
    const int row = blockIdx.x;
    const int tid = threadIdx.x;
    {
        float2 t = *(const float2*)(x + (size_t)row * DM + 2 * tid);
        *(float2*)(sx + 2 * tid) = t;
    }
    __syncthreads();
    const int w = tid >> 5, l = tid & 31;
    const float* wrow = Wb + (size_t)w * DM;
    float s = 0.f;
#pragma unroll
    for (int i = 0; i < 8; i++) {
        int kb = i * 128 + l * 4;
        float4 wv = *(const float4*)(wrow + kb);
        float4 xv = *(const float4*)(sx + kb);
        s += wv.x * xv.x + wv.y * xv.y + wv.z * xv.z + wv.w * xv.w;
    }
#pragma unroll
    for (int o = 16; o; o >>= 1) s += __shfl_xor_sync(0xffffffffu, s, o);
    if (l == 0) g_beta[(size_t)row * NH + w] = 1.f / (1.f + expf(-s));
}

// ---------------- per-row inverse RMS ----------------------------------------
__global__ __launch_bounds__(256)
void row_rms_kernel()
{
    __shared__ float red[8];
    const int row = blockIdx.x;
    const int tid = threadIdx.x;
    const int l = tid & 31, wd = tid >> 5;
    float4 x = ((const float4*)(g_attn + (size_t)row * DM))[tid];
    float s = x.x * x.x + x.y * x.y + x.z * x.z + x.w * x.w;
#pragma unroll
    for (int o = 16; o; o >>= 1) s += __shfl_xor_sync(0xffffffffu, s, o);
    if (l == 0) red[wd] = s;
    __syncthreads();
    if (tid == 0) {
        float t = red[0] + red[1] + red[2] + red[3] + red[4] + red[5] + red[6] + red[7];
        g_invrms[row] = rsqrtf(t * (1.f / DM) + 1e-6f);
    }
}

// ======================= chunked delta-rule recurrence =======================
// Per head: M[h,d] (64x64). Per step (reference semantics):
//   out[d] = sum_h q[h]M[h,d]; retr[h] = sum_d M[h,d]k[d];
//   delta = v - retr; M[h,d] += beta*k[h]*delta[d].
// Chunked (T=64): A0 = V - K M^T; ZB solve; Delta = A0 - tril(ZB^T)K;
//   M += K^T diag(beta) Delta; Out = Q M0 + tril_strict(QK^T) diag(beta) Delta.

// --- 64x64x64 fp32 GEMM helpers on 256 threads, smem tiles pitch CP ---
// NT: C[i][j] op= sum_k A[i][k]*B[j][k]   (op: 0 assign, 1 add, 2 subtract)
__device__ __forceinline__ void gemm64_nt(float* __restrict__ Cm,
                                          const float* __restrict__ A,
                                          const float* __restrict__ B, int op)
{
    const int ty = threadIdx.x >> 4, tx = threadIdx.x & 15;
    float acc[4][4];
#pragma unroll
    for (int r = 0; r < 4; r++)
#pragma unroll
        for (int c = 0; c < 4; c++) acc[r][c] = 0.f;

    for (int k4 = 0; k4 < TT; k4 += 4) {
        float4 a[4], b[4];
#pragma unroll
        for (int r = 0; r < 4; r++) a[r] = *(const float4*)&A[(4 * ty + r) * CP + k4];
#pragma unroll
        for (int c = 0; c < 4; c++) b[c] = *(const float4*)&B[(4 * tx + c) * CP + k4];
#pragma unroll
        for (int r = 0; r < 4; r++)
#pragma unroll
            for (int c = 0; c < 4; c++)
                acc[r][c] += a[r].x * b[c].x + a[r].y * b[c].y
                           + a[r].z * b[c].z + a[r].w * b[c].w;
    }
#pragma unroll
    for (int r = 0; r < 4; r++)
#pragma unroll
        for (int c = 0; c < 4; c++) {
            float* p = &Cm[(4 * ty + r) * CP + 4 * tx + c];
            if (op == 0) *p = acc[r][c];
            else if (op == 1) *p += acc[r][c];
            else *p -= acc[r][c];
        }
}

// TN: C[i][j] op= sum_k fA(k,i)*B[k][j], fA = A[k][i] (opt. masked k<i, scaled rs[k])
__device__ __forceinline__ void gemm64_tn(float* __restrict__ Cm,
                                          const float* __restrict__ A,
                                          const float* __restrict__ B, int op,
                                          int strict_mask, const float* __restrict__ rs)
{
    const int ty = threadIdx.x >> 4, tx = threadIdx.x & 15;
    float acc[4][4];
#pragma unroll
    for (int r = 0; r < 4; r++)
#pragma unroll
        for (int c = 0; c < 4; c++) acc[r][c] = 0.f;

    for (int k = 0; k < TT; k++) {
        float s = rs ? rs[k] : 1.f;
        float a[4];
#pragma unroll
        for (int r = 0; r < 4; r++) {
            int i = 4 * ty + r;
            float av = A[k * CP + i];
            if (strict_mask && k >= i) av = 0.f;
            a[r] = av * s;
        }
        float4 b = *(const float4*)&B[k * CP + 4 * tx];
#pragma unroll
        for (int r = 0; r < 4; r++) {
            acc[r][0] = fmaf(a[r], b.x, acc[r][0]);
            acc[r][1] = fmaf(a[r], b.y, acc[r][1]);
            acc[r][2] = fmaf(a[r], b.z, acc[r][2]);
            acc[r][3] = fmaf(a[r], b.w, acc[r][3]);
        }
    }
#pragma unroll
    for (int r = 0; r < 4; r++)
#pragma unroll
        for (int c = 0; c < 4; c++) {
            float* p = &Cm[(4 * ty + r) * CP + 4 * tx + c];
            if (op == 0) *p = acc[r][c];
            else if (op == 1) *p += acc[r][c];
            else *p -= acc[r][c];
        }
}

// load/store 64x64 fp32 tile (global row stride grs floats <-> smem pitch CP)
__device__ __forceinline__ void load_tile(float* __restrict__ dst,
                                          const float* __restrict__ g, int grs)
{
    for (int i = threadIdx.x; i < TT * 16; i += 256) {
        int t = i >> 4, f = (i & 15) << 2;
        *(float4*)&dst[t * CP + f] = *(const float4*)&g[(size_t)t * grs + f];
    }
}
__device__ __forceinline__ void store_tile(const float* __restrict__ src,
                                           float* __restrict__ g, int grs)
{
    for (int i = threadIdx.x; i < TT * 16; i += 256) {
        int t = i >> 4, f = (i & 15) << 2;
        *(float4*)&g[(size_t)t * grs + f] = *(const float4*)&src[t * CP + f];
    }
}

// Kernel A: per (chunk, head) gram CC = K K^T   (fully parallel, 2048 CTAs)
__global__ __launch_bounds__(256)
void chunk_pre()
{
    const int hg = blockIdx.y, c = blockIdx.x;
    const int b = hg >> 4, n = hg & 15;
    __shared__ __align__(16) float sK[TT * CP];
    __shared__ __align__(16) float sC[TT * CP];
    const size_t gbase = ((size_t)(b * SS + c * TT) * NH + n) * HD;
    load_tile(sK, g_k + gbase, NH * HD);
    __syncthreads();
    gemm64_nt(sC, sK, sK, 0);
    __syncthreads();
    store_tile(sC, g_CC + ((size_t)hg * NCH + c) * TT * TT, TT);
}

// Kernel B: sequential over chunks, 64 CTAs (one per head)
__global__ __launch_bounds__(256, 1)
void chunk_seq()
{
    extern __shared__ float sm[];
    float* sM = sm;                 // state M[h][d]
    float* sK = sm + TT * CP;
    float* sV = sm + 2 * TT * CP;   // V -> A0 -> Delta
    float* sZ = sm + 3 * TT * CP;   // Bb -> ZB (in place)
    float* sC = sm + 4 * TT * CP;   // CC
    float* sb = sm + 5 * TT * CP;   // beta[64]

    const int hg = blockIdx.x;
    const int b = hg >> 4, n = hg & 15;
    const int tid = threadIdx.x;

    for (int i = tid; i < TT * CP; i += 256) sM[i] = 0.f;
    __syncthreads();

    for (int c = 0; c < NCH; c++) {
        const size_t gbase = ((size_t)(b * SS + c * TT) * NH + n) * HD;
        load_tile(sK, g_k + gbase, NH * HD);
        load_tile(sV, g_v + gbase, NH * HD);
        load_tile(sC, g_CC + ((size_t)hg * NCH + c) * TT * TT, TT);
        if (tid < TT) sb[tid] = g_beta[(size_t)(b * SS + c * TT + tid) * NH + n];
        // snapshot M0 TRANSPOSED: g_M0[d*64+h] = M[h][d]  (coalesced in h)
        {
            float* gm = g_M0 + ((size_t)hg * NCH + c) * HD * HD;
            for (int i = tid; i < HD * HD; i += 256) {
                int h = i & 63, d = i >> 6;
                gm[(size_t)d * HD + h] = sM[h * CP + d];
            }
        }
        __syncthreads();

        // A0 = V - NT(K, M)   [t][h] -= sum_d K[t,d]M[h,d]
        gemm64_nt(sV, sK, sM, 2);
        __syncthreads();
        // Bb = NT(A0, K)      [i][t] = sum_h A0[i,h]K[t,h]
        gemm64_nt(sZ, sV, sK, 0);
        __syncthreads();

        // forward solve (in place Bb->ZB): ZB[i,t] = beta_i*(Bb[i,t] - sum_{j<i} ZB[j,i]*CC[j,t])
        {
            const int colz = tid >> 2, rz = tid & 3;
            for (int i = 0; i < TT; i++) {
                float acc = 0.f;
                for (int j = rz; j < i; j += 4)
                    acc = fmaf(sZ[j * CP + i], sC[j * CP + colz], acc);
                acc += __shfl_xor_sync(0xffffffffu, acc, 1);
                acc += __shfl_xor_sync(0xffffffffu, acc, 2);
                if (rz == 0) sZ[i * CP + colz] = sb[i] * (sZ[i * CP + colz] - acc);
                __syncthreads();
            }
        }

        // Delta = A0 - TN(ZB masked j<i, K)   (in place on sV)
        gemm64_tn(sV, sZ, sK, 2, 1, (const float*)0);
        __syncthreads();
        store_tile(sV, g_dlt + ((size_t)hg * NCH + c) * TT * HD, HD);
        // M[h][d] += sum_j beta_j K[j,h] Delta[j,d]
        gemm64_tn(sM, sK, sV, 1, 0, sb);
        __syncthreads();
    }
}

// Kernel C: outputs, fully parallel (2048 CTAs)
// Out = NT(Q, M0T) + TN(beta*mask(j<t)*PT, Delta),  PT = NT(K, Q)
__global__ __launch_bounds__(256)
void chunk_out()
{
    extern __shared__ float sm[];
    float* sQ = sm;
    float* sT = sm + TT * CP;       // M0T / Delta staging? -> M0T
    float* sP = sm + 2 * TT * CP;   // PT
    float* sD = sm + 3 * TT * CP;   // Delta
    float* sO = sm + 4 * TT * CP;   // K, then Out
    float* sb = sm + 5 * TT * CP;   // beta[64]

    const int hg = blockIdx.y, c = blockIdx.x;
    const int b = hg >> 4, n = hg & 15;
    const int tid = threadIdx.x;
    const size_t gbase = ((size_t)(b * SS + c * TT) * NH + n) * HD;

    load_tile(sQ, g_q + gbase, NH * HD);
    load_tile(sO, g_k + gbase, NH * HD);            // K into sO (dst-to-be)
    if (tid < TT) sb[tid] = g_beta[(size_t)(b * SS + c * TT + tid) * NH + n];
    __syncthreads();
    gemm64_nt(sP, sO, sQ, 0);                       // PT[j][t] = sum_h K[j,h]Q[t,h]
    __syncthreads();
    load_tile(sT, g_M0 + ((size_t)hg * NCH + c) * HD * HD, HD);   // M0T[d][h]
    load_tile(sD, g_dlt + ((size_t)hg * NCH + c) * TT * HD, HD);  // Delta[j][d]
    __syncthreads();
    gemm64_nt(sO, sQ, sT, 0);                       // Out1[t][d] = sum_h Q[t,h]M0T[d,h]
    __syncthreads();
    gemm64_tn(sO, sP, sD, 1, 1, sb);                // += sum_{j<t} beta_j PT[j,t] Delta[j,d]
    __syncthreads();
    store_tile(sO, g_attn + gbase, NH * HD);
}

// ---------------- launch ------------------------------------------------------
extern "C" void kernel_launch(void* const* d_in, const int* in_sizes, int n_in,
                              void* d_out, int out_size)
{
    const float* x    = (const float*)d_in[0];
    const float* Wq   = (const float*)d_in[1];
    const float* Wk   = (const float*)d_in[2];
    const float* Wv   = (const float*)d_in[3];
    const float* Wo   = (const float*)d_in[4];
    const float* Wb   = (const float*)d_in[5];
    const float* rmsw = (const float*)d_in[6];
    float* outp = (float*)d_out;

    const int SMEM_DYN = (5 * TT * CP + 64) * 4;   // 87296 B
    cudaFuncSetAttribute(chunk_seq, cudaFuncAttributeMaxDynamicSharedMemorySize, SMEM_DYN);
    cudaFuncSetAttribute(chunk_out, cudaFuncAttributeMaxDynamicSharedMemorySize, SMEM_DYN);

    // one-shot bf16 hi/lo splits
    split_w_kernel<<<dim3(DM * DM / 4 / 256, 4), 256>>>(Wq, Wk, Wv, Wo);
    split_x_kernel<<<MROWS * DM / 4 / 256, 256>>>(x);

    // projections: fused SiLU + l2norm(q,k) on tensor cores (bf16x3)
    mma_qkv<<<dim3(DM / 128, MROWS / 128, 3), 256>>>();
    beta_kernel<<<MROWS, 512>>>(x, Wb);

    // chunked delta-rule recurrence
    chunk_pre<<<dim3(NCH, HG), 256>>>();
    chunk_seq<<<HG, 256, SMEM_DYN>>>();
    chunk_out<<<dim3(NCH, HG), 256, SMEM_DYN>>>();

    // rmsnorm fused into attn split, then output projection
    row_rms_kernel<<<MROWS, 256>>>();
    split_attn_kernel<<<MROWS * DM / 4 / 256, 256>>>(rmsw);
    mma_o<<<dim3(DM / 128, MROWS / 128), 256>>>(outp);
}